// round 2
// baseline (speedup 1.0000x reference)
#include <cuda_runtime.h>
#include <cstdint>

#define DTW_INF 99999.0f

// Tile configuration: T x T tile per block, P threads, W columns per thread.
constexpr int T = 1024;
constexpr int W = 4;
constexpr int P = 256;          // P * W == T
constexpr int NWARP = P / 32;   // 8

// ---------------------------------------------------------------------------
// Init kernel: write RAW boundary values (row 0 and column 0 of the table).
// ---------------------------------------------------------------------------
__global__ void dtw_init_bounds(float* __restrict__ out, int N, int M)
{
    int Mp1 = M + 1;
    int stride = gridDim.x * blockDim.x;
    int idx = blockIdx.x * blockDim.x + threadIdx.x;
    for (int j = idx; j <= M; j += stride)
        out[j] = (j == 0) ? 0.0f : DTW_INF;
    for (int i = idx + 1; i <= N; i += stride)
        out[(size_t)i * Mp1] = DTW_INF;
}

// ---------------------------------------------------------------------------
// Wavefront kernel: one block computes one T x T tile (RAW values into out).
// Launched once per tile anti-diagonal; halos are read raw from `out`.
// Thread t owns W consecutive columns; at step s it computes local row s - t.
// Neighbor (left-boundary) values travel via shfl within a warp and a
// parity-double-buffered shared ring across warp boundaries.
// ---------------------------------------------------------------------------
__global__ __launch_bounds__(P)
void dtw_diag_kernel(const float* __restrict__ x,
                     const float* __restrict__ y,
                     float* __restrict__ out,
                     int N, int M, int d, int it0)
{
    const int It = it0 + blockIdx.x;
    const int Jt = d - It;
    const int R0 = It * T + 1;     // first table row of this tile
    const int C0 = Jt * T + 1;     // first table col of this tile
    const int Mp1 = M + 1;

    __shared__ float shX[T];          // x values for this tile's rows
    __shared__ float shLeft[T + 1];   // raw left halo: v(R0-1+k, C0-1)
    __shared__ float shRing[2][2][NWARP];  // [parity][last/lastprev][warp]

    const int t = threadIdx.x;
    const int lane = t & 31;
    const int warp = t >> 5;

    // Cooperative halo / input staging.
    for (int k = t; k < T; k += P)
        shX[k] = x[R0 - 1 + k];
    for (int k = t; k <= T; k += P)
        shLeft[k] = out[(size_t)(R0 - 1 + k) * Mp1 + (C0 - 1)];

    // Per-thread column data and top halo.
    const int cbase = C0 + t * W;           // first table col owned by thread
    float yv[W], rowvals[W];
#pragma unroll
    for (int c = 0; c < W; c++) {
        yv[c] = y[cbase - 1 + c];
        rowvals[c] = out[(size_t)(R0 - 1) * Mp1 + cbase + c];  // raw top halo
    }
    float lastv = rowvals[W - 1];   // my last-column value of most recent row
    float lastv_prev = lastv;       // ... of the row before that

    __syncthreads();

    const int NSTEPS = T + P - 1;
    for (int s = 0; s < NSTEPS; ++s) {
        // Values produced by the left-neighbor thread at step s-1 / s-2:
        float n_last  = __shfl_up_sync(0xffffffffu, lastv, 1);
        float n_lastp = __shfl_up_sync(0xffffffffu, lastv_prev, 1);
        if (lane == 0) {
            if (warp == 0) {
                // thread 0: left halo from shared (raw values)
                int li = (s < T) ? s : (T - 1);
                n_last  = shLeft[li + 1];   // v(R0+li,   C0-1)
                n_lastp = shLeft[li];       // v(R0+li-1, C0-1)
            } else {
                int pb = (s + 1) & 1;       // parity of step s-1
                n_last  = shRing[pb][0][warp - 1];
                n_lastp = shRing[pb][1][warp - 1];
            }
        }

        const int li = s - t;
        if (0 <= li && li < T) {
            const float xi = shX[li];
            float diag = n_lastp;   // v(i-1, cbase-1)
            float left = n_last;    // v(i,   cbase-1)
            size_t base = (size_t)(R0 + li) * Mp1 + cbase;
#pragma unroll
            for (int c = 0; c < W; c++) {
                float top = rowvals[c];
                float dd = xi - yv[c];
                float m = fminf(fminf(top, diag), left);
                float v = fmaf(dd, dd, m);
                diag = top;
                left = v;
                rowvals[c] = v;
                out[base + c] = v;   // RAW value; sqrt applied in final pass
            }
            lastv_prev = lastv;
            lastv = left;
        }

        if (lane == 31) {
            int pc = s & 1;
            shRing[pc][0][warp] = lastv;
            shRing[pc][1][warp] = lastv_prev;
        }
        __syncthreads();
    }
}

// ---------------------------------------------------------------------------
// Final pass: elementwise sqrt over the whole table (memory bound).
// ---------------------------------------------------------------------------
__global__ void dtw_sqrt_all(float* __restrict__ out, size_t n)
{
    size_t stride = (size_t)gridDim.x * blockDim.x;
    for (size_t k = (size_t)blockIdx.x * blockDim.x + threadIdx.x; k < n; k += stride)
        out[k] = sqrtf(out[k]);
}

// ---------------------------------------------------------------------------
extern "C" void kernel_launch(void* const* d_in, const int* in_sizes, int n_in,
                              void* d_out, int out_size)
{
    const float* x = (const float*)d_in[0];
    const float* y = (const float*)d_in[1];
    float* out = (float*)d_out;
    const int N = in_sizes[0];
    const int M = in_sizes[1];

    dtw_init_bounds<<<64, 256>>>(out, N, M);

    const int NTr = N / T;
    const int NTc = M / T;
    for (int d = 0; d < NTr + NTc - 1; ++d) {
        int it0 = (d - (NTc - 1) > 0) ? (d - (NTc - 1)) : 0;
        int it1 = (d < NTr - 1) ? d : (NTr - 1);
        int width = it1 - it0 + 1;
        dtw_diag_kernel<<<width, P>>>(x, y, out, N, M, d, it0);
    }

    size_t total = (size_t)(N + 1) * (size_t)(M + 1);
    dtw_sqrt_all<<<1024, 256>>>(out, total);
}